// round 16
// baseline (speedup 1.0000x reference)
#include <cuda_runtime.h>
#include <cuda_bf16.h>
#include <cstdint>

// ---------------------------------------------------------------------------
// PhaseTracker: encode(+init) -> evolve -> HMMA GEMM(+fused match)
// ---------------------------------------------------------------------------

#define N_DET   4096
#define DIM     128
#define HID     64
#define NOSC    28
#define KGEMM   192          // 3 blocks of 56 (hi|hi|lo vs hi|lo|hi) padded
#define KTILES  11           // k < 176 (data ends at 168, [168,176) zeroed)
#define TWO_PI_F 6.283185307179586f
#define INV_2PI  0.15915494309189535f
#define DENOM_F  28.000010583006244f   // (sqrt(28)+1e-6)^2

__device__ float g_phase[N_DET * NOSC];
__device__ float g_amp[N_DET * NOSC];
__device__ __align__(16) __nv_bfloat16 g_Abf[N_DET * KGEMM];  // [hi56|hi56|lo56|pad]
__device__ __align__(16) __nv_bfloat16 g_Bbf[N_DET * KGEMM];  // [hi56|lo56|hi56|pad]
__device__ unsigned long long g_rowbest[N_DET];
__device__ unsigned long long g_colbest[N_DET];
__device__ int g_done;

__device__ __forceinline__ float mod2pi(float v) {
    return v - floorf(v * INV_2PI) * TWO_PI_F;
}
__device__ __forceinline__ float softplusf(float x) {
    return fmaxf(x, 0.0f) + log1pf(expf(-fabsf(x)));
}
__device__ __forceinline__ unsigned ordf(float x) {
    unsigned u = __float_as_uint(x);
    return (u & 0x80000000u) ? ~u : (u | 0x80000000u);
}
__device__ __forceinline__ void bf16split(float v, __nv_bfloat16& hi, __nv_bfloat16& lo) {
    hi = __float2bfloat16_rn(v);
    lo = __float2bfloat16_rn(v - __bfloat162float(hi));
}
__device__ __forceinline__ uint32_t smem_u32(const void* p) {
    uint32_t a;
    asm("{ .reg .u64 t; cvta.to.shared.u64 t, %1; cvt.u32.u64 %0, t; }" : "=r"(a) : "l"(p));
    return a;
}
__device__ __forceinline__ void cp_async16(uint32_t smem_addr, const void* gptr) {
    asm volatile("cp.async.cg.shared.global [%0], [%1], 16;"
                 :: "r"(smem_addr), "l"(gptr));
}
__device__ __forceinline__ void cp_async_wait_all() {
    asm volatile("cp.async.commit_group;");
    asm volatile("cp.async.wait_group 0;");
}
__device__ __forceinline__ void ldm_x4(uint32_t* r, uint32_t addr) {
    asm volatile("ldmatrix.sync.aligned.m8n8.x4.shared.b16 {%0,%1,%2,%3}, [%4];"
                 : "=r"(r[0]), "=r"(r[1]), "=r"(r[2]), "=r"(r[3]) : "r"(addr));
}
__device__ __forceinline__ void mma16816(float* c, const uint32_t* a, const uint32_t* b) {
    asm volatile("mma.sync.aligned.m16n8k16.row.col.f32.bf16.bf16.f32 "
                 "{%0,%1,%2,%3}, {%4,%5,%6,%7}, {%8,%9}, {%0,%1,%2,%3};"
                 : "+f"(c[0]), "+f"(c[1]), "+f"(c[2]), "+f"(c[3])
                 : "r"(a[0]), "r"(a[1]), "r"(a[2]), "r"(a[3]), "r"(b[0]), "r"(b[1]));
}

// ---------------------------------------------------------------------------
// Encode (R15-proven): EIGHT rows/thread; init fused into blocks 0-15.
// 256 blocks x 256 threads, 2 iterations of 16 rows.
// ---------------------------------------------------------------------------
#define ENC_W1STR 132
#define ENC_W2STR 68
#define ENC_SMEM_FLOATS (2*HID*ENC_W1STR + 2*NOSC*ENC_W2STR + 2048 + 2048)

__global__ __launch_bounds__(256, 2)
void encode_kernel(const float* __restrict__ det_t, const float* __restrict__ det_t1,
                   const float* __restrict__ Wp1, const float* __restrict__ bp1,
                   const float* __restrict__ Wp2, const float* __restrict__ bp2,
                   const float* __restrict__ Wa1, const float* __restrict__ ba1,
                   const float* __restrict__ Wa2, const float* __restrict__ ba2) {
    extern __shared__ float sm[];
    float* wp1T = sm;
    float* wa1T = wp1T + HID * ENC_W1STR;
    float* wp2T = wa1T + HID * ENC_W1STR;
    float* wa2T = wp2T + NOSC * ENC_W2STR;
    float* xs   = wa2T + NOSC * ENC_W2STR;     // 16 x 128
    float* hs   = xs + 2048;                   // 16 x 128

    int tid = threadIdx.x;

    if (blockIdx.x < 16) {
        int i = blockIdx.x * 256 + tid;
        g_rowbest[i] = 0ull; g_colbest[i] = 0ull;
        uint4 z = make_uint4(0, 0, 0, 0);
        uint4* pa = (uint4*)((char*)g_Abf + (size_t)i * 384 + 336);
        uint4* pb = (uint4*)((char*)g_Bbf + (size_t)i * 384 + 336);
        pa[0] = z; pa[1] = z; pa[2] = z;
        pb[0] = z; pb[1] = z; pb[2] = z;
        if (i == 0) g_done = 0;
    }

    for (int idx = tid; idx < DIM * HID; idx += 256) {
        int k = idx >> 6, j = idx & 63;
        wp1T[j * ENC_W1STR + k] = Wp1[idx];
        wa1T[j * ENC_W1STR + k] = Wa1[idx];
    }
    for (int idx = tid; idx < HID * NOSC; idx += 256) {
        int k = idx / NOSC, j = idx % NOSC;
        wp2T[j * ENC_W2STR + k] = Wp2[idx];
        wa2T[j * ENC_W2STR + k] = Wa2[idx];
    }

    const int quad = tid >> 7;
    const int t    = tid & 127;
    const int rb0  = 8 * quad;                 // local rows rb0..rb0+7

    for (int it = 0; it < 2; ++it) {
        int rowbase = blockIdx.x * 32 + it * 16;
        bool isT = rowbase < N_DET;
        const float* X = isT ? (det_t + (size_t)rowbase * DIM)
                             : (det_t1 + (size_t)(rowbase - N_DET) * DIM);
        __syncthreads();
        {
            const float4* s4 = (const float4*)X;
            float4* x4 = (float4*)xs;
            x4[tid] = s4[tid];
            x4[tid + 256] = s4[tid + 256];     // 16 rows x 128 floats
        }
        __syncthreads();

        // ---- layer 1: 8 rows per thread ----
        {
            bool doAmp = (t >= 64);
            if (!doAmp || isT) {
                int j = doAmp ? (t - 64) : t;
                const float4* w4 = (const float4*)(doAmp ? &wa1T[j * ENC_W1STR]
                                                         : &wp1T[j * ENC_W1STR]);
                const float4* xp[8];
                float a[8];
                float b = doAmp ? ba1[j] : bp1[j];
                #pragma unroll
                for (int r = 0; r < 8; ++r) {
                    xp[r] = (const float4*)(xs + (rb0 + r) * 128);
                    a[r] = b;
                }
                #pragma unroll
                for (int k4 = 0; k4 < 32; ++k4) {
                    float4 w = w4[k4];
                    #pragma unroll
                    for (int r = 0; r < 8; ++r) {
                        float4 v = xp[r][k4];
                        a[r] += w.x * v.x + w.y * v.y + w.z * v.z + w.w * v.w;
                    }
                }
                #pragma unroll
                for (int r = 0; r < 8; ++r)
                    hs[(rb0 + r) * 128 + t] = fmaxf(a[r], 0.0f);
            }
        }
        __syncthreads();

        // ---- layer 2: 8 rows per thread ----
        int lane = t & 31, wgrp = t >> 5;
        if (wgrp == 0 && lane < NOSC) {               // phase head
            const float4* w4 = (const float4*)&wp2T[lane * ENC_W2STR];
            const float4* hp[8];
            float p[8];
            float b = bp2[lane];
            #pragma unroll
            for (int r = 0; r < 8; ++r) {
                hp[r] = (const float4*)(hs + (rb0 + r) * 128);
                p[r] = b;
            }
            #pragma unroll
            for (int k4 = 0; k4 < 16; ++k4) {
                float4 w = w4[k4];
                #pragma unroll
                for (int r = 0; r < 8; ++r) {
                    float4 v = hp[r][k4];
                    p[r] += w.x * v.x + w.y * v.y + w.z * v.z + w.w * v.w;
                }
            }
            if (isT) {
                #pragma unroll
                for (int r = 0; r < 8; ++r)
                    g_phase[(rowbase + rb0 + r) * NOSC + lane] = mod2pi(p[r]);
            } else {
                // B' row layout: [cos_hi28 sin_hi28 | cos_lo28 sin_lo28 | cos_hi28 sin_hi28]
                #pragma unroll
                for (int r = 0; r < 8; ++r) {
                    int cc = rowbase - N_DET + rb0 + r;
                    float ph = mod2pi(p[r]);
                    float cv = cosf(ph), sv = sinf(ph);
                    __nv_bfloat16 chi, clo, shi, slo;
                    bf16split(cv, chi, clo); bf16split(sv, shi, slo);
                    __nv_bfloat16* br = g_Bbf + (size_t)cc * KGEMM;
                    br[lane] = chi;       br[28 + lane] = shi;
                    br[56 + lane] = clo;  br[84 + lane] = slo;
                    br[112 + lane] = chi; br[140 + lane] = shi;
                }
            }
        } else if (wgrp == 1 && lane < NOSC && isT) { // amp head
            const float4* w4 = (const float4*)&wa2T[lane * ENC_W2STR];
            const float4* hp[8];
            float p[8];
            float b = ba2[lane];
            #pragma unroll
            for (int r = 0; r < 8; ++r) {
                hp[r] = (const float4*)(hs + (rb0 + r) * 128 + 64);   // +64 floats = ha
                p[r] = b;
            }
            #pragma unroll
            for (int k4 = 0; k4 < 16; ++k4) {
                float4 w = w4[k4];
                #pragma unroll
                for (int r = 0; r < 8; ++r) {
                    float4 v = hp[r][k4];
                    p[r] += w.x * v.x + w.y * v.y + w.z * v.z + w.w * v.w;
                }
            }
            #pragma unroll
            for (int r = 0; r < 8; ++r)
                g_amp[(rowbase + rb0 + r) * NOSC + lane] = softplusf(p[r]);
        }
    }
}

// ---------------------------------------------------------------------------
// Evolve (proven): 5 Kuramoto steps, one warp per row.
// ---------------------------------------------------------------------------
__global__ void evolve_kernel() {
    int gw   = (blockIdx.x * blockDim.x + threadIdx.x) >> 5;
    int lane = threadIdx.x & 31;
    if (gw >= N_DET) return;
    bool act = lane < NOSC;

    float ph = act ? g_phase[gw * NOSC + lane] : 0.0f;
    float am = act ? g_amp[gw * NOSC + lane] : 0.0f;
    float omega = TWO_PI_F * (lane < 4 ? 2.0f : (lane < 12 ? 6.0f : 40.0f));

    #pragma unroll
    for (int s = 0; s < 5; ++s) {
        float c  = act ? cosf(ph) : 0.0f;
        float sn = act ? sinf(ph) : 0.0f;
        float sc = c, ss = sn;
        #pragma unroll
        for (int off = 16; off; off >>= 1) {
            sc += __shfl_down_sync(0xFFFFFFFFu, sc, off);
            ss += __shfl_down_sync(0xFFFFFFFFu, ss, off);
        }
        sc = __shfl_sync(0xFFFFFFFFu, sc, 0);
        ss = __shfl_sync(0xFFFFFFFFu, ss, 0);
        float mc = sc / 28.0f, ms = ss / 28.0f;
        float coup = ms * c - mc * sn;
        ph = mod2pi(ph + 0.01f * (omega + am * coup));
    }
    if (act) {
        float c = cosf(ph), sn = sinf(ph);
        __nv_bfloat16 chi, clo, shi, slo;
        bf16split(c, chi, clo); bf16split(sn, shi, slo);
        __nv_bfloat16* ar = g_Abf + (size_t)gw * KGEMM;
        ar[lane] = chi;       ar[28 + lane] = shi;
        ar[56 + lane] = chi;  ar[84 + lane] = shi;
        ar[112 + lane] = clo; ar[140 + lane] = slo;
    }
}

// ---------------------------------------------------------------------------
// HMMA GEMM (R15 shape, cp.async staging) + last-CTA fused match (R14-proven).
// 128x128 tile/CTA, 8 warps (4x2), warp = 32x64, 2 CTAs/SM, grid (32,32).
// ---------------------------------------------------------------------------
#define GT_ROWB   368
#define GT_TILE   (128 * GT_ROWB)           // 47104
#define GT_SMEM_TOTAL (2 * GT_TILE)         // 94208

__global__ __launch_bounds__(256, 2)
void gemm_kernel(float* __restrict__ sim, float* __restrict__ matches) {
    extern __shared__ char smg[];
    const int tid = threadIdx.x;
    const int lane = tid & 31;
    const int w = tid >> 5;
    const int warpRow = w & 3;        // 0..3  (32 rows each)
    const int warpCol = w >> 2;       // 0..1  (64 cols each)
    uint32_t smA = smem_u32(smg);
    uint32_t smB = smA + GT_TILE;

    // ---- stage tiles via cp.async: 22 chunks of 16B per row (K<176) ----
    {
        const char* srcA = (const char*)(g_Abf + (size_t)blockIdx.y * 128 * KGEMM);
        const char* srcB = (const char*)(g_Bbf + (size_t)blockIdx.x * 128 * KGEMM);
        #pragma unroll
        for (int i = 0; i < 22; ++i) {
            int idx = tid + i * 256;          // 0..5631
            int half = idx >= 2816;
            int e = half ? idx - 2816 : idx;
            int r = e / 22, q = e - r * 22;
            int off = r * GT_ROWB + q * 16;
            int goff = r * 384 + q * 16;
            if (half) cp_async16(smB + off, srcB + goff);
            else      cp_async16(smA + off, srcA + goff);
        }
        cp_async_wait_all();
    }
    __syncthreads();

    float acc[2][8][4];
    #pragma unroll
    for (int mt = 0; mt < 2; ++mt)
        #pragma unroll
        for (int nt = 0; nt < 8; ++nt)
            #pragma unroll
            for (int e = 0; e < 4; ++e) acc[mt][nt][e] = 0.0f;

    const uint32_t aBase = smA + (warpRow * 32 + (lane & 15)) * GT_ROWB + (lane >> 4) * 16;
    const uint32_t bBase = smB + (warpCol * 64 + (lane & 7) + (lane >> 4) * 8) * GT_ROWB
                               + ((lane >> 3) & 1) * 16;

    #pragma unroll 2
    for (int kt = 0; kt < KTILES; ++kt) {
        uint32_t af[2][4];
        uint32_t bq[4][4];
        #pragma unroll
        for (int mt = 0; mt < 2; ++mt)
            ldm_x4(af[mt], aBase + mt * 16 * GT_ROWB + kt * 32);
        #pragma unroll
        for (int p = 0; p < 4; ++p)
            ldm_x4(bq[p], bBase + p * 16 * GT_ROWB + kt * 32);
        #pragma unroll
        for (int mt = 0; mt < 2; ++mt)
            #pragma unroll
            for (int p = 0; p < 4; ++p) {
                mma16816(acc[mt][2 * p],     af[mt], &bq[p][0]);
                mma16816(acc[mt][2 * p + 1], af[mt], &bq[p][2]);
            }
    }

    const float invden = 1.0f / DENOM_F;
    const int g = lane >> 2, tq = lane & 3;
    const int rowg = blockIdx.y * 128 + warpRow * 32 + g;
    const int colg = blockIdx.x * 128 + warpCol * 64 + tq * 2;

    #pragma unroll
    for (int mt = 0; mt < 2; ++mt) {
        int r0 = rowg + mt * 16;
        int r1 = r0 + 8;
        unsigned long long best0 = 0ull, best1 = 0ull;
        #pragma unroll
        for (int nt = 0; nt < 8; ++nt) {
            int col = colg + nt * 8;
            float2 v0, v1;
            v0.x = acc[mt][nt][0] * invden; v0.y = acc[mt][nt][1] * invden;
            v1.x = acc[mt][nt][2] * invden; v1.y = acc[mt][nt][3] * invden;
            *(float2*)(sim + (size_t)r0 * N_DET + col) = v0;
            *(float2*)(sim + (size_t)r1 * N_DET + col) = v1;
            unsigned long long k;
            k = ((unsigned long long)ordf(v0.x) << 32) | (unsigned)(~(unsigned)col);
            if (k > best0) best0 = k;
            k = ((unsigned long long)ordf(v0.y) << 32) | (unsigned)(~(unsigned)(col + 1));
            if (k > best0) best0 = k;
            k = ((unsigned long long)ordf(v1.x) << 32) | (unsigned)(~(unsigned)col);
            if (k > best1) best1 = k;
            k = ((unsigned long long)ordf(v1.y) << 32) | (unsigned)(~(unsigned)(col + 1));
            if (k > best1) best1 = k;
        }
        #pragma unroll
        for (int off = 1; off < 4; off <<= 1) {
            unsigned long long o0 = __shfl_xor_sync(0xFFFFFFFFu, best0, off);
            unsigned long long o1 = __shfl_xor_sync(0xFFFFFFFFu, best1, off);
            if (o0 > best0) best0 = o0;
            if (o1 > best1) best1 = o1;
        }
        if (tq == 0) {
            atomicMax(&g_rowbest[r0], best0);
            atomicMax(&g_rowbest[r1], best1);
        }
    }

    // ---- last-CTA fused match (R14-proven pattern) ----
    __threadfence();
    __syncthreads();
    __shared__ int s_last;
    if (tid == 0) s_last = (atomicAdd(&g_done, 1) == 1023) ? 1 : 0;
    __syncthreads();
    if (!s_last) return;

    const unsigned ORD_THR = __float_as_uint(0.3f) | 0x80000000u;
    unsigned long long rb[16];
    unsigned long long ck[16];
    unsigned jj[16];
    bool el[16];
    #pragma unroll
    for (int r = 0; r < 16; ++r) {
        int i = tid + r * 256;
        rb[r] = g_rowbest[i];
        el[r] = ((unsigned)(rb[r] >> 32) > ORD_THR);
        if (el[r]) {
            jj[r] = ~(unsigned)rb[r];
            ck[r] = (rb[r] & 0xFFFFFFFF00000000ull) | (unsigned)(~(unsigned)i);
            atomicMax(&g_colbest[jj[r]], ck[r]);
        }
    }
    __threadfence();
    __syncthreads();
    #pragma unroll
    for (int r = 0; r < 16; ++r) {
        int i = tid + r * 256;
        float m = -1.0f;
        if (el[r] && g_colbest[jj[r]] == ck[r]) m = (float)jj[r];
        matches[i] = m;
    }
}

// ---------------------------------------------------------------------------
extern "C" void kernel_launch(void* const* d_in, const int* in_sizes, int n_in,
                              void* d_out, int out_size) {
    const float* det_t  = (const float*)d_in[0];
    const float* det_t1 = (const float*)d_in[1];
    const float* Wp1 = (const float*)d_in[2];
    const float* bp1 = (const float*)d_in[3];
    const float* Wp2 = (const float*)d_in[4];
    const float* bp2 = (const float*)d_in[5];
    const float* Wa1 = (const float*)d_in[6];
    const float* ba1 = (const float*)d_in[7];
    const float* Wa2 = (const float*)d_in[8];
    const float* ba2 = (const float*)d_in[9];
    float* out = (float*)d_out;                 // [0,4096): matches, then sim

    cudaFuncSetAttribute(encode_kernel, cudaFuncAttributeMaxDynamicSharedMemorySize,
                         ENC_SMEM_FLOATS * 4);
    cudaFuncSetAttribute(gemm_kernel, cudaFuncAttributeMaxDynamicSharedMemorySize,
                         GT_SMEM_TOTAL);

    encode_kernel<<<256, 256, ENC_SMEM_FLOATS * 4>>>(det_t, det_t1,
                                                     Wp1, bp1, Wp2, bp2,
                                                     Wa1, ba1, Wa2, ba2);
    evolve_kernel<<<512, 256>>>();
    gemm_kernel<<<dim3(32, 32), 256, GT_SMEM_TOTAL>>>(out + N_DET, out);
}

// round 17
// speedup vs baseline: 1.1978x; 1.1978x over previous
#include <cuda_runtime.h>
#include <cuda_bf16.h>
#include <cstdint>

// ---------------------------------------------------------------------------
// PhaseTracker: encode(+init, t1 fast path) -> evolve -> HMMA GEMM -> match
// ---------------------------------------------------------------------------

#define N_DET   4096
#define DIM     128
#define HID     64
#define NOSC    28
#define KGEMM   192          // 3 blocks of 56 (hi|hi|lo vs hi|lo|hi) padded
#define KTILES  11           // k < 176 (data ends at 168, [168,176) zeroed)
#define TWO_PI_F 6.283185307179586f
#define INV_2PI  0.15915494309189535f
#define DENOM_F  28.000010583006244f   // (sqrt(28)+1e-6)^2

__device__ float g_phase[N_DET * NOSC];
__device__ float g_amp[N_DET * NOSC];
__device__ __align__(16) __nv_bfloat16 g_Abf[N_DET * KGEMM];  // [hi56|hi56|lo56|pad]
__device__ __align__(16) __nv_bfloat16 g_Bbf[N_DET * KGEMM];  // [hi56|lo56|hi56|pad]
__device__ unsigned long long g_rowbest[N_DET];
__device__ unsigned long long g_colbest[N_DET];
__device__ int g_bar1;
__device__ int g_bar2;

__device__ __forceinline__ float mod2pi(float v) {
    return v - floorf(v * INV_2PI) * TWO_PI_F;
}
__device__ __forceinline__ float softplusf(float x) {
    return fmaxf(x, 0.0f) + log1pf(expf(-fabsf(x)));
}
__device__ __forceinline__ unsigned ordf(float x) {
    unsigned u = __float_as_uint(x);
    return (u & 0x80000000u) ? ~u : (u | 0x80000000u);
}
__device__ __forceinline__ void bf16split(float v, __nv_bfloat16& hi, __nv_bfloat16& lo) {
    hi = __float2bfloat16_rn(v);
    lo = __float2bfloat16_rn(v - __bfloat162float(hi));
}
__device__ __forceinline__ uint32_t smem_u32(const void* p) {
    uint32_t a;
    asm("{ .reg .u64 t; cvta.to.shared.u64 t, %1; cvt.u32.u64 %0, t; }" : "=r"(a) : "l"(p));
    return a;
}
__device__ __forceinline__ void ldm_x4(uint32_t* r, uint32_t addr) {
    asm volatile("ldmatrix.sync.aligned.m8n8.x4.shared.b16 {%0,%1,%2,%3}, [%4];"
                 : "=r"(r[0]), "=r"(r[1]), "=r"(r[2]), "=r"(r[3]) : "r"(addr));
}
__device__ __forceinline__ void mma16816(float* c, const uint32_t* a, const uint32_t* b) {
    asm volatile("mma.sync.aligned.m16n8k16.row.col.f32.bf16.bf16.f32 "
                 "{%0,%1,%2,%3}, {%4,%5,%6,%7}, {%8,%9}, {%0,%1,%2,%3};"
                 : "+f"(c[0]), "+f"(c[1]), "+f"(c[2]), "+f"(c[3])
                 : "r"(a[0]), "r"(a[1]), "r"(a[2]), "r"(a[3]), "r"(b[0]), "r"(b[1]));
}

// ---------------------------------------------------------------------------
// Encode: 256 blocks x 256 threads, 2 iterations of 16 rows.
// Blocks 0-127 = detections_t (proven 8-rows/thread dual-MLP path).
// Blocks 128-255 = detections_t1 (NEW fast path: all threads on phase MLP,
// 4 rows/thread in layer 1, all 8 warps x 2 rows in layer 2).
// ---------------------------------------------------------------------------
#define ENC_W1STR 132
#define ENC_W2STR 68
#define ENC_SMEM_FLOATS (2*HID*ENC_W1STR + 2*NOSC*ENC_W2STR + 2048 + 2048)

__global__ __launch_bounds__(256, 2)
void encode_kernel(const float* __restrict__ det_t, const float* __restrict__ det_t1,
                   const float* __restrict__ Wp1, const float* __restrict__ bp1,
                   const float* __restrict__ Wp2, const float* __restrict__ bp2,
                   const float* __restrict__ Wa1, const float* __restrict__ ba1,
                   const float* __restrict__ Wa2, const float* __restrict__ ba2) {
    extern __shared__ float sm[];
    float* wp1T = sm;
    float* wa1T = wp1T + HID * ENC_W1STR;
    float* wp2T = wa1T + HID * ENC_W1STR;
    float* wa2T = wp2T + NOSC * ENC_W2STR;
    float* xs   = wa2T + NOSC * ENC_W2STR;     // 16 x 128
    float* hs   = xs + 2048;                   // 16 x 128

    int tid = threadIdx.x;
    const bool isT = blockIdx.x < 128;

    if (blockIdx.x < 16) {
        int i = blockIdx.x * 256 + tid;
        g_rowbest[i] = 0ull; g_colbest[i] = 0ull;
        uint4 z = make_uint4(0, 0, 0, 0);
        uint4* pa = (uint4*)((char*)g_Abf + (size_t)i * 384 + 336);
        uint4* pb = (uint4*)((char*)g_Bbf + (size_t)i * 384 + 336);
        pa[0] = z; pa[1] = z; pa[2] = z;
        pb[0] = z; pb[1] = z; pb[2] = z;
        if (i == 0) { g_bar1 = 0; g_bar2 = 0; }
    }

    // stage weights (t1 blocks skip amp weights)
    for (int idx = tid; idx < DIM * HID; idx += 256) {
        int k = idx >> 6, j = idx & 63;
        wp1T[j * ENC_W1STR + k] = Wp1[idx];
        if (isT) wa1T[j * ENC_W1STR + k] = Wa1[idx];
    }
    for (int idx = tid; idx < HID * NOSC; idx += 256) {
        int k = idx / NOSC, j = idx % NOSC;
        wp2T[j * ENC_W2STR + k] = Wp2[idx];
        if (isT) wa2T[j * ENC_W2STR + k] = Wa2[idx];
    }

    const int quad = tid >> 7;
    const int t    = tid & 127;
    const int rb0  = 8 * quad;                 // t path: local rows rb0..rb0+7

    for (int it = 0; it < 2; ++it) {
        int rowbase = blockIdx.x * 32 + it * 16;
        const float* X = isT ? (det_t + (size_t)rowbase * DIM)
                             : (det_t1 + (size_t)(rowbase - N_DET) * DIM);
        __syncthreads();
        {
            const float4* s4 = (const float4*)X;
            float4* x4 = (float4*)xs;
            x4[tid] = s4[tid];
            x4[tid + 256] = s4[tid + 256];     // 16 rows x 128 floats
        }
        __syncthreads();

        if (isT) {
            // ---- layer 1 (t path, proven): 8 rows per thread ----
            {
                bool doAmp = (t >= 64);
                int j = doAmp ? (t - 64) : t;
                const float4* w4 = (const float4*)(doAmp ? &wa1T[j * ENC_W1STR]
                                                         : &wp1T[j * ENC_W1STR]);
                const float4* xp[8];
                float a[8];
                float b = doAmp ? ba1[j] : bp1[j];
                #pragma unroll
                for (int r = 0; r < 8; ++r) {
                    xp[r] = (const float4*)(xs + (rb0 + r) * 128);
                    a[r] = b;
                }
                #pragma unroll
                for (int k4 = 0; k4 < 32; ++k4) {
                    float4 w = w4[k4];
                    #pragma unroll
                    for (int r = 0; r < 8; ++r) {
                        float4 v = xp[r][k4];
                        a[r] += w.x * v.x + w.y * v.y + w.z * v.z + w.w * v.w;
                    }
                }
                #pragma unroll
                for (int r = 0; r < 8; ++r)
                    hs[(rb0 + r) * 128 + t] = fmaxf(a[r], 0.0f);
            }
            __syncthreads();

            // ---- layer 2 (t path, proven): 8 rows per thread ----
            int lane = t & 31, wgrp = t >> 5;
            if (wgrp == 0 && lane < NOSC) {               // phase head
                const float4* w4 = (const float4*)&wp2T[lane * ENC_W2STR];
                const float4* hp[8];
                float p[8];
                float b = bp2[lane];
                #pragma unroll
                for (int r = 0; r < 8; ++r) {
                    hp[r] = (const float4*)(hs + (rb0 + r) * 128);
                    p[r] = b;
                }
                #pragma unroll
                for (int k4 = 0; k4 < 16; ++k4) {
                    float4 w = w4[k4];
                    #pragma unroll
                    for (int r = 0; r < 8; ++r) {
                        float4 v = hp[r][k4];
                        p[r] += w.x * v.x + w.y * v.y + w.z * v.z + w.w * v.w;
                    }
                }
                #pragma unroll
                for (int r = 0; r < 8; ++r)
                    g_phase[(rowbase + rb0 + r) * NOSC + lane] = mod2pi(p[r]);
            } else if (wgrp == 1 && lane < NOSC) {        // amp head
                const float4* w4 = (const float4*)&wa2T[lane * ENC_W2STR];
                const float4* hp[8];
                float p[8];
                float b = ba2[lane];
                #pragma unroll
                for (int r = 0; r < 8; ++r) {
                    hp[r] = (const float4*)(hs + (rb0 + r) * 128 + 64);   // ha
                    p[r] = b;
                }
                #pragma unroll
                for (int k4 = 0; k4 < 16; ++k4) {
                    float4 w = w4[k4];
                    #pragma unroll
                    for (int r = 0; r < 8; ++r) {
                        float4 v = hp[r][k4];
                        p[r] += w.x * v.x + w.y * v.y + w.z * v.z + w.w * v.w;
                    }
                }
                #pragma unroll
                for (int r = 0; r < 8; ++r)
                    g_amp[(rowbase + rb0 + r) * NOSC + lane] = softplusf(p[r]);
            }
        } else {
            // ---- layer 1 (t1 fast path): all threads on phase, 4 rows each ----
            {
                int j  = t & 63;
                int g2 = (quad << 1) | (t >> 6);          // 0..3 -> rows 4*g2..4*g2+3
                const float4* w4 = (const float4*)&wp1T[j * ENC_W1STR];
                const float4* xp[4];
                float a[4];
                float b = bp1[j];
                #pragma unroll
                for (int r = 0; r < 4; ++r) {
                    xp[r] = (const float4*)(xs + (4 * g2 + r) * 128);
                    a[r] = b;
                }
                #pragma unroll
                for (int k4 = 0; k4 < 32; ++k4) {
                    float4 w = w4[k4];
                    #pragma unroll
                    for (int r = 0; r < 4; ++r) {
                        float4 v = xp[r][k4];
                        a[r] += w.x * v.x + w.y * v.y + w.z * v.z + w.w * v.w;
                    }
                }
                #pragma unroll
                for (int r = 0; r < 4; ++r)
                    hs[(4 * g2 + r) * 128 + j] = fmaxf(a[r], 0.0f);
            }
            __syncthreads();

            // ---- layer 2 (t1 fast path): all 8 warps, 2 rows each ----
            int lane = tid & 31, wid = tid >> 5;          // wid 0..7
            if (lane < NOSC) {
                const float4* w4 = (const float4*)&wp2T[lane * ENC_W2STR];
                int r0 = 2 * wid, r1 = r0 + 1;
                const float4* h0 = (const float4*)(hs + r0 * 128);
                const float4* h1 = (const float4*)(hs + r1 * 128);
                float b = bp2[lane];
                float p0 = b, p1 = b;
                #pragma unroll
                for (int k4 = 0; k4 < 16; ++k4) {
                    float4 w = w4[k4];
                    float4 va = h0[k4], vb = h1[k4];
                    p0 += w.x * va.x + w.y * va.y + w.z * va.z + w.w * va.w;
                    p1 += w.x * vb.x + w.y * vb.y + w.z * vb.z + w.w * vb.w;
                }
                // B' row layout: [cos_hi28 sin_hi28 | cos_lo28 sin_lo28 | cos_hi28 sin_hi28]
                #pragma unroll
                for (int rr = 0; rr < 2; ++rr) {
                    int row = (rr == 0) ? r0 : r1;
                    float ph = mod2pi(rr == 0 ? p0 : p1);
                    int cc = rowbase - N_DET + row;
                    float cv = cosf(ph), sv = sinf(ph);
                    __nv_bfloat16 chi, clo, shi, slo;
                    bf16split(cv, chi, clo); bf16split(sv, shi, slo);
                    __nv_bfloat16* br = g_Bbf + (size_t)cc * KGEMM;
                    br[lane] = chi;       br[28 + lane] = shi;
                    br[56 + lane] = clo;  br[84 + lane] = slo;
                    br[112 + lane] = chi; br[140 + lane] = shi;
                }
            }
        }
    }
}

// ---------------------------------------------------------------------------
// Evolve (proven): 5 Kuramoto steps, one warp per row.
// ---------------------------------------------------------------------------
__global__ void evolve_kernel() {
    int gw   = (blockIdx.x * blockDim.x + threadIdx.x) >> 5;
    int lane = threadIdx.x & 31;
    if (gw >= N_DET) return;
    bool act = lane < NOSC;

    float ph = act ? g_phase[gw * NOSC + lane] : 0.0f;
    float am = act ? g_amp[gw * NOSC + lane] : 0.0f;
    float omega = TWO_PI_F * (lane < 4 ? 2.0f : (lane < 12 ? 6.0f : 40.0f));

    #pragma unroll
    for (int s = 0; s < 5; ++s) {
        float c  = act ? cosf(ph) : 0.0f;
        float sn = act ? sinf(ph) : 0.0f;
        float sc = c, ss = sn;
        #pragma unroll
        for (int off = 16; off; off >>= 1) {
            sc += __shfl_down_sync(0xFFFFFFFFu, sc, off);
            ss += __shfl_down_sync(0xFFFFFFFFu, ss, off);
        }
        sc = __shfl_sync(0xFFFFFFFFu, sc, 0);
        ss = __shfl_sync(0xFFFFFFFFu, ss, 0);
        float mc = sc / 28.0f, ms = ss / 28.0f;
        float coup = ms * c - mc * sn;
        ph = mod2pi(ph + 0.01f * (omega + am * coup));
    }
    if (act) {
        float c = cosf(ph), sn = sinf(ph);
        __nv_bfloat16 chi, clo, shi, slo;
        bf16split(c, chi, clo); bf16split(sn, shi, slo);
        __nv_bfloat16* ar = g_Abf + (size_t)gw * KGEMM;
        ar[lane] = chi;       ar[28 + lane] = shi;
        ar[56 + lane] = chi;  ar[84 + lane] = shi;
        ar[112 + lane] = clo; ar[140 + lane] = slo;
    }
}

// ---------------------------------------------------------------------------
// HMMA GEMM (R15-proven, LDG staging): 128x128 tile/CTA, 8 warps (4x2),
// warp = 32x64, 2 CTAs/SM. Fused rowbest epilogue.
// ---------------------------------------------------------------------------
#define GT_ROWB   368
#define GT_TILE   (128 * GT_ROWB)           // 47104
#define GT_SMEM_TOTAL (2 * GT_TILE)         // 94208

__global__ __launch_bounds__(256, 2)
void gemm_kernel(float* __restrict__ sim) {
    extern __shared__ char smg[];
    const int tid = threadIdx.x;
    const int lane = tid & 31;
    const int w = tid >> 5;
    const int warpRow = w & 3;        // 0..3  (32 rows each)
    const int warpCol = w >> 2;       // 0..1  (64 cols each)
    uint32_t smA = smem_u32(smg);
    uint32_t smB = smA + GT_TILE;

    {
        const uint4* srcA = (const uint4*)(g_Abf + (size_t)blockIdx.y * 128 * KGEMM);
        const uint4* srcB = (const uint4*)(g_Bbf + (size_t)blockIdx.x * 128 * KGEMM);
        #pragma unroll
        for (int i = 0; i < 22; ++i) {
            int idx = tid + i * 256;          // 0..5631
            int half = idx >= 2816;
            int e = half ? idx - 2816 : idx;
            int r = e / 22, q = e - r * 22;
            int off = r * GT_ROWB + q * 16;
            if (half) *(uint4*)(smg + GT_TILE + off) = srcB[r * 24 + q];
            else      *(uint4*)(smg + off) = srcA[r * 24 + q];
        }
    }
    __syncthreads();

    float acc[2][8][4];
    #pragma unroll
    for (int mt = 0; mt < 2; ++mt)
        #pragma unroll
        for (int nt = 0; nt < 8; ++nt)
            #pragma unroll
            for (int e = 0; e < 4; ++e) acc[mt][nt][e] = 0.0f;

    const uint32_t aBase = smA + (warpRow * 32 + (lane & 15)) * GT_ROWB + (lane >> 4) * 16;
    const uint32_t bBase = smB + (warpCol * 64 + (lane & 7) + (lane >> 4) * 8) * GT_ROWB
                               + ((lane >> 3) & 1) * 16;

    #pragma unroll 2
    for (int kt = 0; kt < KTILES; ++kt) {
        uint32_t af[2][4];
        uint32_t bq[4][4];
        #pragma unroll
        for (int mt = 0; mt < 2; ++mt)
            ldm_x4(af[mt], aBase + mt * 16 * GT_ROWB + kt * 32);
        #pragma unroll
        for (int p = 0; p < 4; ++p)
            ldm_x4(bq[p], bBase + p * 16 * GT_ROWB + kt * 32);
        #pragma unroll
        for (int mt = 0; mt < 2; ++mt)
            #pragma unroll
            for (int p = 0; p < 4; ++p) {
                mma16816(acc[mt][2 * p],     af[mt], &bq[p][0]);
                mma16816(acc[mt][2 * p + 1], af[mt], &bq[p][2]);
            }
    }

    const float invden = 1.0f / DENOM_F;
    const int g = lane >> 2, tq = lane & 3;
    const int rowg = blockIdx.y * 128 + warpRow * 32 + g;
    const int colg = blockIdx.x * 128 + warpCol * 64 + tq * 2;

    #pragma unroll
    for (int mt = 0; mt < 2; ++mt) {
        int r0 = rowg + mt * 16;
        int r1 = r0 + 8;
        unsigned long long best0 = 0ull, best1 = 0ull;
        #pragma unroll
        for (int nt = 0; nt < 8; ++nt) {
            int col = colg + nt * 8;
            float2 v0, v1;
            v0.x = acc[mt][nt][0] * invden; v0.y = acc[mt][nt][1] * invden;
            v1.x = acc[mt][nt][2] * invden; v1.y = acc[mt][nt][3] * invden;
            *(float2*)(sim + (size_t)r0 * N_DET + col) = v0;
            *(float2*)(sim + (size_t)r1 * N_DET + col) = v1;
            unsigned long long k;
            k = ((unsigned long long)ordf(v0.x) << 32) | (unsigned)(~(unsigned)col);
            if (k > best0) best0 = k;
            k = ((unsigned long long)ordf(v0.y) << 32) | (unsigned)(~(unsigned)(col + 1));
            if (k > best0) best0 = k;
            k = ((unsigned long long)ordf(v1.x) << 32) | (unsigned)(~(unsigned)col);
            if (k > best1) best1 = k;
            k = ((unsigned long long)ordf(v1.y) << 32) | (unsigned)(~(unsigned)(col + 1));
            if (k > best1) best1 = k;
        }
        #pragma unroll
        for (int off = 1; off < 4; off <<= 1) {
            unsigned long long o0 = __shfl_xor_sync(0xFFFFFFFFu, best0, off);
            unsigned long long o1 = __shfl_xor_sync(0xFFFFFFFFu, best1, off);
            if (o0 > best0) best0 = o0;
            if (o1 > best1) best1 = o1;
        }
        if (tq == 0) {
            atomicMax(&g_rowbest[r0], best0);
            atomicMax(&g_rowbest[r1], best1);
        }
    }
}

// ---------------------------------------------------------------------------
// Match: claim + software grid barrier + resolve. 4 blocks x 1024 threads.
// ---------------------------------------------------------------------------
__global__ void match_kernel(float* __restrict__ matches) {
    int i = blockIdx.x * 1024 + threadIdx.x;
    const unsigned ORD_THR = __float_as_uint(0.3f) | 0x80000000u;

    unsigned long long rb = g_rowbest[i];
    unsigned ordsim = (unsigned)(rb >> 32);
    unsigned long long claimkey = 0ull;
    unsigned j = 0;
    bool eligible = (ordsim > ORD_THR);
    if (eligible) {
        j = ~(unsigned)rb;
        claimkey = (rb & 0xFFFFFFFF00000000ull) | (unsigned)(~(unsigned)i);
        atomicMax(&g_colbest[j], claimkey);
    }
    __threadfence();
    __syncthreads();

    if (threadIdx.x == 0) atomicAdd(&g_bar1, 1);
    while (*(volatile int*)&g_bar1 < 4) { }
    __threadfence();

    float m = -1.0f;
    if (eligible && g_colbest[j] == claimkey) m = (float)j;
    matches[i] = m;

    __syncthreads();
    if (threadIdx.x == 0) {
        int old = atomicAdd(&g_bar2, 1);
        if (old == 3) { g_bar1 = 0; g_bar2 = 0; }
    }
}

// ---------------------------------------------------------------------------
extern "C" void kernel_launch(void* const* d_in, const int* in_sizes, int n_in,
                              void* d_out, int out_size) {
    const float* det_t  = (const float*)d_in[0];
    const float* det_t1 = (const float*)d_in[1];
    const float* Wp1 = (const float*)d_in[2];
    const float* bp1 = (const float*)d_in[3];
    const float* Wp2 = (const float*)d_in[4];
    const float* bp2 = (const float*)d_in[5];
    const float* Wa1 = (const float*)d_in[6];
    const float* ba1 = (const float*)d_in[7];
    const float* Wa2 = (const float*)d_in[8];
    const float* ba2 = (const float*)d_in[9];
    float* out = (float*)d_out;                 // [0,4096): matches, then sim

    cudaFuncSetAttribute(encode_kernel, cudaFuncAttributeMaxDynamicSharedMemorySize,
                         ENC_SMEM_FLOATS * 4);
    cudaFuncSetAttribute(gemm_kernel, cudaFuncAttributeMaxDynamicSharedMemorySize,
                         GT_SMEM_TOTAL);

    encode_kernel<<<256, 256, ENC_SMEM_FLOATS * 4>>>(det_t, det_t1,
                                                     Wp1, bp1, Wp2, bp2,
                                                     Wa1, ba1, Wa2, ba2);
    evolve_kernel<<<512, 256>>>();
    gemm_kernel<<<dim3(32, 32), 256, GT_SMEM_TOTAL>>>(out + N_DET);
    match_kernel<<<4, 1024>>>(out);
}